// round 1
// baseline (speedup 1.0000x reference)
#include <cuda_runtime.h>
#include <cuda_bf16.h>
#include <math.h>

#define N_NODES  100000
#define N_TOTAL  150000
#define D_IN     512
#define H_LAT    256
#define N_CLASS  40
#define NNZ      4800000
#define NUM_LAYERS 3

// ---------------- device scratch (static globals: no allocation allowed) ----
__device__ float g_cur [(size_t)N_TOTAL * H_LAT];
__device__ float g_next[(size_t)N_TOTAL * H_LAT];
__device__ float g_acc [(size_t)N_TOTAL * H_LAT];
__device__ int   g_col [NNZ];
__device__ float g_val [NNZ];
__device__ int   g_rowptr[N_TOTAL + 1];
__device__ int   g_cursor[N_TOTAL];
__device__ int   g_counts[N_TOTAL];
__device__ int   g_bsum[256];
__device__ int   g_boff[256];

// ---------------- small helpers ---------------------------------------------
__device__ __forceinline__ unsigned long long bcast2(float x) {
    unsigned long long r; unsigned u = __float_as_uint(x);
    asm("mov.b64 %0, {%1, %1};" : "=l"(r) : "r"(u));
    return r;
}
__device__ __forceinline__ void fma2(unsigned long long &c, unsigned long long a, unsigned long long b) {
    asm("fma.rn.f32x2 %0, %1, %2, %0;" : "+l"(c) : "l"(a), "l"(b));
}
__device__ __forceinline__ float2 unpack2(unsigned long long v) {
    float2 f;
    f.x = __uint_as_float((unsigned)v);
    f.y = __uint_as_float((unsigned)(v >> 32));
    return f;
}

// ---------------- CSR build --------------------------------------------------
__global__ void k_zero_counts() {
    int i = blockIdx.x * blockDim.x + threadIdx.x;
    if (i < N_TOTAL) g_counts[i] = 0;
}
__global__ void k_hist(const int* __restrict__ rows) {
    int i = blockIdx.x * blockDim.x + threadIdx.x;
    if (i < NNZ) atomicAdd(&g_counts[rows[i]], 1);
}
// per-block exclusive scan (1024/block), writes local exclusive + block totals
__global__ void k_scan_a() {
    __shared__ int s[1024];
    int tid = threadIdx.x;
    int i = blockIdx.x * 1024 + tid;
    int v = (i < N_TOTAL) ? g_counts[i] : 0;
    s[tid] = v;
    __syncthreads();
    #pragma unroll
    for (int off = 1; off < 1024; off <<= 1) {
        int t = (tid >= off) ? s[tid - off] : 0;
        __syncthreads();
        s[tid] += t;
        __syncthreads();
    }
    if (i < N_TOTAL) g_rowptr[i] = s[tid] - v;   // local exclusive
    if (tid == 1023) g_bsum[blockIdx.x] = s[1023];
}
__global__ void k_scan_b(int nblk) {
    __shared__ int sb[256];
    int tid = threadIdx.x;
    if (tid < nblk) sb[tid] = g_bsum[tid];
    __syncthreads();
    if (tid == 0) {
        int run = 0;
        for (int i = 0; i < nblk; i++) { int t = sb[i]; sb[i] = run; run += t; }
    }
    __syncthreads();
    if (tid < nblk) g_boff[tid] = sb[tid];
}
__global__ void k_scan_c() {
    int tid = threadIdx.x;
    int i = blockIdx.x * 1024 + tid;
    if (i < N_TOTAL) {
        int v = g_rowptr[i] + g_boff[blockIdx.x];
        g_rowptr[i] = v;
        g_cursor[i] = v;
    }
    if (i == 0) g_rowptr[N_TOTAL] = NNZ;
}
__global__ void k_fill(const int* __restrict__ rows, const int* __restrict__ cols,
                       const float* __restrict__ vals) {
    int i = blockIdx.x * blockDim.x + threadIdx.x;
    if (i < NNZ) {
        int r = rows[i];
        int p = atomicAdd(&g_cursor[r], 1);
        g_col[p] = cols[i];
        g_val[p] = vals[i];
    }
}

// ---------------- dense GEMM: emb = X @ W_red + b_red -----------------------
// 128x64 tile, 256 threads (16x16), micro-tile 8(m) x 4(n) using f32x2 FMAs.
__global__ __launch_bounds__(256) void k_gemm(const float* __restrict__ X,
                                              const float* __restrict__ W,
                                              const float* __restrict__ bias) {
    __shared__ __align__(16) float As[16][132];  // [k][m], padded
    __shared__ __align__(16) float Bs[16][64];   // [k][n]
    const int tx = threadIdx.x, ty = threadIdx.y;
    const int tid = ty * 16 + tx;
    const int m0 = blockIdx.x * 128;
    const int n0 = blockIdx.y * 64;

    unsigned long long c[4][4] = {};

    for (int k0 = 0; k0 < D_IN; k0 += 16) {
        // load A tile 128x16 (2 float4 per thread)
        #pragma unroll
        for (int it = 0; it < 2; it++) {
            int idx = tid + it * 256;           // 0..511
            int m = idx >> 2;
            int kq = idx & 3;
            int mg = m0 + m;
            float4 av = make_float4(0.f, 0.f, 0.f, 0.f);
            if (mg < N_TOTAL)
                av = *(const float4*)(X + (size_t)mg * D_IN + k0 + kq * 4);
            As[kq * 4 + 0][m] = av.x;
            As[kq * 4 + 1][m] = av.y;
            As[kq * 4 + 2][m] = av.z;
            As[kq * 4 + 3][m] = av.w;
        }
        // load B tile 16x64 (1 float4 per thread)
        {
            int k = tid >> 4;
            int nq = tid & 15;
            float4 bv = *(const float4*)(W + (size_t)(k0 + k) * H_LAT + n0 + nq * 4);
            *(float4*)&Bs[k][nq * 4] = bv;
        }
        __syncthreads();

        #pragma unroll
        for (int ks = 0; ks < 16; ks++) {
            ulonglong2 a01 = *(const ulonglong2*)&As[ks][ty * 8];
            ulonglong2 a23 = *(const ulonglong2*)&As[ks][ty * 8 + 4];
            float4 bv = *(const float4*)&Bs[ks][tx * 4];
            unsigned long long b0 = bcast2(bv.x);
            unsigned long long b1 = bcast2(bv.y);
            unsigned long long b2 = bcast2(bv.z);
            unsigned long long b3 = bcast2(bv.w);
            fma2(c[0][0], a01.x, b0); fma2(c[0][1], a01.x, b1);
            fma2(c[0][2], a01.x, b2); fma2(c[0][3], a01.x, b3);
            fma2(c[1][0], a01.y, b0); fma2(c[1][1], a01.y, b1);
            fma2(c[1][2], a01.y, b2); fma2(c[1][3], a01.y, b3);
            fma2(c[2][0], a23.x, b0); fma2(c[2][1], a23.x, b1);
            fma2(c[2][2], a23.x, b2); fma2(c[2][3], a23.x, b3);
            fma2(c[3][0], a23.y, b0); fma2(c[3][1], a23.y, b1);
            fma2(c[3][2], a23.y, b2); fma2(c[3][3], a23.y, b3);
        }
        __syncthreads();
    }

    const float4 bv = *(const float4*)(bias + n0 + tx * 4);
    #pragma unroll
    for (int q = 0; q < 4; q++) {
        float2 u0 = unpack2(c[q][0]);
        float2 u1 = unpack2(c[q][1]);
        float2 u2 = unpack2(c[q][2]);
        float2 u3 = unpack2(c[q][3]);
        #pragma unroll
        for (int h = 0; h < 2; h++) {
            int m = m0 + ty * 8 + q * 2 + h;
            if (m < N_TOTAL) {
                float4 v;
                v.x = (h ? u0.y : u0.x) + bv.x;
                v.y = (h ? u1.y : u1.x) + bv.y;
                v.z = (h ? u2.y : u2.x) + bv.z;
                v.w = (h ? u3.y : u3.x) + bv.w;
                size_t off = (size_t)m * H_LAT + n0 + tx * 4;
                *(float4*)&g_cur[off] = v;
                *(float4*)&g_acc[off] = v;
            }
        }
    }
}

// ---------------- SpMM layer: next = A @ cur; acc += next -------------------
// Feature-chunked (64 cols per blockIdx.y) so the gathered slice stays in L2.
__global__ __launch_bounds__(256) void k_spmm(int flip) {
    const float* __restrict__ cur = flip ? g_next : g_cur;
    float* __restrict__ nxt = flip ? g_cur : g_next;

    int r = blockIdx.x * 4 + threadIdx.y;
    int f = blockIdx.y * 64 + threadIdx.x;

    int e0 = g_rowptr[r];
    int e1 = g_rowptr[r + 1];

    float s0 = 0.f, s1 = 0.f, s2 = 0.f, s3 = 0.f;
    int e = e0;
    for (; e + 3 < e1; e += 4) {
        int   c0 = g_col[e],     c1 = g_col[e + 1], c2 = g_col[e + 2], c3 = g_col[e + 3];
        float v0 = g_val[e],     v1 = g_val[e + 1], v2 = g_val[e + 2], v3 = g_val[e + 3];
        s0 += v0 * __ldg(&cur[(size_t)c0 * H_LAT + f]);
        s1 += v1 * __ldg(&cur[(size_t)c1 * H_LAT + f]);
        s2 += v2 * __ldg(&cur[(size_t)c2 * H_LAT + f]);
        s3 += v3 * __ldg(&cur[(size_t)c3 * H_LAT + f]);
    }
    for (; e < e1; e++) {
        s0 += g_val[e] * __ldg(&cur[(size_t)g_col[e] * H_LAT + f]);
    }
    float s = (s0 + s1) + (s2 + s3);
    size_t off = (size_t)r * H_LAT + f;
    nxt[off] = s;
    g_acc[off] += s;
}

// ---------------- classifier + log_softmax ----------------------------------
// block (40 classes, 8 thread-rows), each thread handles 8 node-rows -> 64/block
__global__ void k_classify(const float* __restrict__ Wc, const float* __restrict__ bc,
                           float* __restrict__ out) {
    __shared__ float zsh[64][41];
    __shared__ float red[64];
    const int tx = threadIdx.x;             // class 0..39
    const int ty = threadIdx.y;             // 0..7
    const int r0 = blockIdx.x * 64 + ty * 8;

    int rr[8];
    #pragma unroll
    for (int i = 0; i < 8; i++) {
        int r = r0 + i;
        rr[i] = (r < N_NODES) ? r : (N_NODES - 1);
    }

    float s[8] = {0.f, 0.f, 0.f, 0.f, 0.f, 0.f, 0.f, 0.f};
    for (int k = 0; k < H_LAT; k += 4) {
        float w0 = Wc[(k + 0) * N_CLASS + tx];
        float w1 = Wc[(k + 1) * N_CLASS + tx];
        float w2 = Wc[(k + 2) * N_CLASS + tx];
        float w3 = Wc[(k + 3) * N_CLASS + tx];
        #pragma unroll
        for (int i = 0; i < 8; i++) {
            const float4 a = *(const float4*)&g_acc[(size_t)rr[i] * H_LAT + k];
            s[i] += a.x * w0 + a.y * w1 + a.z * w2 + a.w * w3;
        }
    }
    const float b = bc[tx];
    #pragma unroll
    for (int i = 0; i < 8; i++) {
        zsh[ty * 8 + i][tx] = s[i] * 0.25f + b;   // out = acc / (NUM_LAYERS+1)
    }
    __syncthreads();

    int t = ty * 40 + tx;
    if (t < 64) {
        int gr = blockIdx.x * 64 + t;
        if (gr < N_NODES) {
            float m = zsh[t][0];
            #pragma unroll
            for (int cc = 1; cc < N_CLASS; cc++) m = fmaxf(m, zsh[t][cc]);
            float se = 0.f;
            #pragma unroll
            for (int cc = 0; cc < N_CLASS; cc++) se += expf(zsh[t][cc] - m);
            red[t] = m + logf(se);
        }
    }
    __syncthreads();

    #pragma unroll
    for (int i = 0; i < 8; i++) {
        int r = r0 + i;
        if (r < N_NODES)
            out[(size_t)r * N_CLASS + tx] = zsh[ty * 8 + i][tx] - red[ty * 8 + i];
    }
}

// ---------------- launch -----------------------------------------------------
extern "C" void kernel_launch(void* const* d_in, const int* in_sizes, int n_in,
                              void* d_out, int out_size) {
    const float* X     = (const float*)d_in[0];
    const float* W_red = (const float*)d_in[1];
    const float* b_red = (const float*)d_in[2];
    const float* W_cls = (const float*)d_in[3];
    const float* b_cls = (const float*)d_in[4];
    const float* evals = (const float*)d_in[5];
    const int*   erows = (const int*)  d_in[6];
    const int*   ecols = (const int*)  d_in[7];
    float* out = (float*)d_out;

    const int NBLK_SCAN = (N_TOTAL + 1023) / 1024;   // 147

    // CSR build
    k_zero_counts<<<(N_TOTAL + 255) / 256, 256>>>();
    k_hist<<<(NNZ + 255) / 256, 256>>>(erows);
    k_scan_a<<<NBLK_SCAN, 1024>>>();
    k_scan_b<<<1, 256>>>(NBLK_SCAN);
    k_scan_c<<<NBLK_SCAN, 1024>>>();
    k_fill<<<(NNZ + 255) / 256, 256>>>(erows, ecols, evals);

    // emb = X @ W_red + b_red  -> g_cur, g_acc
    dim3 gB(16, 16);
    dim3 gG((N_TOTAL + 127) / 128, H_LAT / 64);
    k_gemm<<<gG, gB>>>(X, W_red, b_red);

    // 3 propagation layers
    dim3 sB(64, 4);
    dim3 sG(N_TOTAL / 4, H_LAT / 64);
    for (int l = 0; l < NUM_LAYERS; l++)
        k_spmm<<<sG, sB>>>(l & 1);

    // classify + log_softmax
    dim3 cB(N_CLASS, 8);
    k_classify<<<(N_NODES + 63) / 64, cB>>>(W_cls, b_cls, out);
}

// round 3
// speedup vs baseline: 1.7559x; 1.7559x over previous
#include <cuda_runtime.h>
#include <cuda_bf16.h>
#include <math.h>

#define N_NODES  100000
#define N_TOTAL  150000
#define D_IN     512
#define H_LAT    256
#define N_CLASS  40
#define NNZ      4800000
#define NUM_LAYERS 3

// ---------------- device scratch -------------------------------------------
__device__ float    g_emb [(size_t)N_TOTAL * H_LAT];        // fp32 emb (acc base)
__device__ unsigned g_embh[(size_t)N_TOTAL * (H_LAT/2)];    // emb as bf16x2
__device__ unsigned g_ch0 [(size_t)N_TOTAL * (H_LAT/2)];    // layer outputs bf16x2
__device__ unsigned g_ch1 [(size_t)N_TOTAL * (H_LAT/2)];
__device__ unsigned g_ch2 [(size_t)N_TOTAL * (H_LAT/2)];
__device__ float    g_accn[(size_t)N_NODES * H_LAT];        // acc for node rows
__device__ int2     g_edge[NNZ];                            // packed (col, val)
__device__ int      g_rowptr[N_TOTAL + 1];
__device__ int      g_cursor[N_TOTAL];
__device__ int      g_counts[N_TOTAL];
__device__ int      g_bsum[256];
__device__ int      g_boff[256];

// ---------------- helpers ---------------------------------------------------
__device__ __forceinline__ float bf_lo(unsigned h) { return __uint_as_float(h << 16); }
__device__ __forceinline__ float bf_hi(unsigned h) { return __uint_as_float(h & 0xffff0000u); }
__device__ __forceinline__ unsigned bf_pack(float x, float y) {
    __nv_bfloat162 b = __float22bfloat162_rn(make_float2(x, y));
    return *reinterpret_cast<unsigned*>(&b);
}
__device__ __forceinline__ unsigned f2tf32(float f) {
    unsigned r; asm("cvt.rna.tf32.f32 %0, %1;" : "=r"(r) : "f"(f)); return r;
}
__device__ __forceinline__ void mma_tf32(float* c, const unsigned* a, const unsigned* b) {
    asm("mma.sync.aligned.m16n8k8.row.col.f32.tf32.tf32.f32 "
        "{%0,%1,%2,%3},{%4,%5,%6,%7},{%8,%9},{%0,%1,%2,%3};"
        : "+f"(c[0]), "+f"(c[1]), "+f"(c[2]), "+f"(c[3])
        : "r"(a[0]), "r"(a[1]), "r"(a[2]), "r"(a[3]), "r"(b[0]), "r"(b[1]));
}

// ---------------- CSR build --------------------------------------------------
__global__ void k_zero_counts() {
    int i = blockIdx.x * blockDim.x + threadIdx.x;
    if (i < N_TOTAL) g_counts[i] = 0;
}
__global__ void k_hist(const int* __restrict__ rows) {
    int i = blockIdx.x * blockDim.x + threadIdx.x;
    if (i < NNZ) atomicAdd(&g_counts[rows[i]], 1);
}
__global__ void k_scan_a() {
    __shared__ int s[1024];
    int tid = threadIdx.x;
    int i = blockIdx.x * 1024 + tid;
    int v = (i < N_TOTAL) ? g_counts[i] : 0;
    s[tid] = v;
    __syncthreads();
    #pragma unroll
    for (int off = 1; off < 1024; off <<= 1) {
        int t = (tid >= off) ? s[tid - off] : 0;
        __syncthreads();
        s[tid] += t;
        __syncthreads();
    }
    if (i < N_TOTAL) g_rowptr[i] = s[tid] - v;
    if (tid == 1023) g_bsum[blockIdx.x] = s[1023];
}
__global__ void k_scan_b(int nblk) {
    __shared__ int sb[256];
    int tid = threadIdx.x;
    if (tid < nblk) sb[tid] = g_bsum[tid];
    __syncthreads();
    if (tid == 0) {
        int run = 0;
        for (int i = 0; i < nblk; i++) { int t = sb[i]; sb[i] = run; run += t; }
    }
    __syncthreads();
    if (tid < nblk) g_boff[tid] = sb[tid];
}
__global__ void k_scan_c() {
    int tid = threadIdx.x;
    int i = blockIdx.x * 1024 + tid;
    if (i < N_TOTAL) {
        int v = g_rowptr[i] + g_boff[blockIdx.x];
        g_rowptr[i] = v;
        g_cursor[i] = v;
    }
    if (i == 0) g_rowptr[N_TOTAL] = NNZ;
}
__global__ void k_fill(const int* __restrict__ rows, const int* __restrict__ cols,
                       const float* __restrict__ vals) {
    int i = blockIdx.x * blockDim.x + threadIdx.x;
    if (i < NNZ) {
        int r = rows[i];
        int p = atomicAdd(&g_cursor[r], 1);
        g_edge[p] = make_int2(cols[i], __float_as_int(vals[i]));
    }
}

// ---------------- tf32 tensor-core GEMM: emb = X @ W_red + b_red ------------
// block tile 128(M) x 64(N), 256 thr = 8 warps in 4(M) x 2(N), warp tile 32x32
__global__ __launch_bounds__(256) void k_gemm(const float* __restrict__ X,
                                              const float* __restrict__ W,
                                              const float* __restrict__ bias) {
    __shared__ unsigned As[128][36];   // [m][k], pad 36 -> conflict-free frags
    __shared__ unsigned Bs[32][68];    // [k][n], pad 68

    const int tid  = threadIdx.x;
    const int lane = tid & 31;
    const int warp = tid >> 5;
    const int g  = lane >> 2;          // group id 0..7
    const int t  = lane & 3;           // thread in group 0..3
    const int wm = warp & 3;           // 0..3
    const int wn = warp >> 2;          // 0..1
    const int m0 = blockIdx.y * 128;   // y = M so consecutive blocks share X via L2
    const int n0 = blockIdx.x * 64;

    float acc[2][4][4];
    #pragma unroll
    for (int i = 0; i < 2; i++)
        #pragma unroll
        for (int j = 0; j < 4; j++)
            #pragma unroll
            for (int k = 0; k < 4; k++) acc[i][j][k] = 0.f;

    for (int k0 = 0; k0 < D_IN; k0 += 32) {
        // A tile: 128 x 32 floats (1024 float4), 4 per thread
        #pragma unroll
        for (int it = 0; it < 4; it++) {
            int idx = it * 256 + tid;
            int m = idx >> 3, kq = idx & 7;
            int mg = m0 + m;
            float4 v = make_float4(0.f, 0.f, 0.f, 0.f);
            if (mg < N_TOTAL)
                v = *(const float4*)(X + (size_t)mg * D_IN + k0 + kq * 4);
            uint4 u = make_uint4(f2tf32(v.x), f2tf32(v.y), f2tf32(v.z), f2tf32(v.w));
            *(uint4*)&As[m][kq * 4] = u;
        }
        // B tile: 32 x 64 floats (512 float4), 2 per thread
        #pragma unroll
        for (int it = 0; it < 2; it++) {
            int idx = it * 256 + tid;
            int k = idx >> 4, nq = idx & 15;
            float4 v = *(const float4*)(W + (size_t)(k0 + k) * H_LAT + n0 + nq * 4);
            uint4 u = make_uint4(f2tf32(v.x), f2tf32(v.y), f2tf32(v.z), f2tf32(v.w));
            *(uint4*)&Bs[k][nq * 4] = u;
        }
        __syncthreads();

        #pragma unroll
        for (int kk = 0; kk < 32; kk += 8) {
            unsigned a[2][4], b[4][2];
            #pragma unroll
            for (int mt = 0; mt < 2; mt++) {
                int rb = wm * 32 + mt * 16 + g;
                a[mt][0] = As[rb][kk + t];
                a[mt][1] = As[rb + 8][kk + t];
                a[mt][2] = As[rb][kk + t + 4];
                a[mt][3] = As[rb + 8][kk + t + 4];
            }
            #pragma unroll
            for (int nt = 0; nt < 4; nt++) {
                int cb = wn * 32 + nt * 8 + g;
                b[nt][0] = Bs[kk + t][cb];
                b[nt][1] = Bs[kk + t + 4][cb];
            }
            #pragma unroll
            for (int mt = 0; mt < 2; mt++)
                #pragma unroll
                for (int nt = 0; nt < 4; nt++)
                    mma_tf32(acc[mt][nt], a[mt], b[nt]);
        }
        __syncthreads();
    }

    // epilogue: + bias, write fp32 emb and bf16x2 embh
    #pragma unroll
    for (int nt = 0; nt < 4; nt++) {
        int col = n0 + wn * 32 + nt * 8 + 2 * t;
        float2 bi = *(const float2*)(bias + col);
        #pragma unroll
        for (int mt = 0; mt < 2; mt++) {
            int r0 = m0 + wm * 32 + mt * 16 + g;
            float vx = acc[mt][nt][0] + bi.x;
            float vy = acc[mt][nt][1] + bi.y;
            if (r0 < N_TOTAL) {
                *(float2*)&g_emb[(size_t)r0 * H_LAT + col] = make_float2(vx, vy);
                g_embh[(size_t)r0 * (H_LAT/2) + (col >> 1)] = bf_pack(vx, vy);
            }
            int r1 = r0 + 8;
            float wx = acc[mt][nt][2] + bi.x;
            float wy = acc[mt][nt][3] + bi.y;
            if (r1 < N_TOTAL) {
                *(float2*)&g_emb[(size_t)r1 * H_LAT + col] = make_float2(wx, wy);
                g_embh[(size_t)r1 * (H_LAT/2) + (col >> 1)] = bf_pack(wx, wy);
            }
        }
    }
}

// ---------------- SpMM layer (bf16 gather, bf16 output) ---------------------
// block (64,4): 64 threads over 64 bf16x2 pairs (128 feats), 4 rows per block
__global__ __launch_bounds__(256) void k_spmm(int layer) {
    const unsigned* __restrict__ in  = (layer == 0) ? g_embh : (layer == 1 ? g_ch0 : g_ch1);
    unsigned* __restrict__       out = (layer == 0) ? g_ch0  : (layer == 1 ? g_ch1 : g_ch2);

    int r  = blockIdx.x * 4 + threadIdx.y;
    int f2 = blockIdx.y * 64 + threadIdx.x;

    int e0 = g_rowptr[r];
    int e1 = g_rowptr[r + 1];

    float ax0 = 0.f, ay0 = 0.f, ax1 = 0.f, ay1 = 0.f;
    float ax2 = 0.f, ay2 = 0.f, ax3 = 0.f, ay3 = 0.f;
    int e = e0;
    for (; e + 3 < e1; e += 4) {
        int2 p0 = g_edge[e], p1 = g_edge[e + 1], p2 = g_edge[e + 2], p3 = g_edge[e + 3];
        unsigned h0 = __ldg(&in[(size_t)p0.x * (H_LAT/2) + f2]);
        unsigned h1 = __ldg(&in[(size_t)p1.x * (H_LAT/2) + f2]);
        unsigned h2 = __ldg(&in[(size_t)p2.x * (H_LAT/2) + f2]);
        unsigned h3 = __ldg(&in[(size_t)p3.x * (H_LAT/2) + f2]);
        float v0 = __int_as_float(p0.y), v1 = __int_as_float(p1.y);
        float v2 = __int_as_float(p2.y), v3 = __int_as_float(p3.y);
        ax0 += v0 * bf_lo(h0); ay0 += v0 * bf_hi(h0);
        ax1 += v1 * bf_lo(h1); ay1 += v1 * bf_hi(h1);
        ax2 += v2 * bf_lo(h2); ay2 += v2 * bf_hi(h2);
        ax3 += v3 * bf_lo(h3); ay3 += v3 * bf_hi(h3);
    }
    for (; e < e1; e++) {
        int2 p = g_edge[e];
        unsigned h = __ldg(&in[(size_t)p.x * (H_LAT/2) + f2]);
        float v = __int_as_float(p.y);
        ax0 += v * bf_lo(h); ay0 += v * bf_hi(h);
    }
    float sx = (ax0 + ax1) + (ax2 + ax3);
    float sy = (ay0 + ay1) + (ay2 + ay3);
    out[(size_t)r * (H_LAT/2) + f2] = bf_pack(sx, sy);
}

// ---------------- accsum: accn = emb + c1 + c2 + c3 (node rows only) --------
__global__ void k_accsum() {
    int i = blockIdx.x * blockDim.x + threadIdx.x;   // pair index
    const int NP = N_NODES * (H_LAT / 2);
    if (i < NP) {
        float2 e = ((const float2*)g_emb)[i];
        unsigned h0 = g_ch0[i], h1 = g_ch1[i], h2 = g_ch2[i];
        e.x += bf_lo(h0) + bf_lo(h1) + bf_lo(h2);
        e.y += bf_hi(h0) + bf_hi(h1) + bf_hi(h2);
        ((float2*)g_accn)[i] = e;
    }
}

// ---------------- classifier + log_softmax ----------------------------------
__global__ void k_classify(const float* __restrict__ Wc, const float* __restrict__ bc,
                           float* __restrict__ out) {
    __shared__ float zsh[64][41];
    __shared__ float red[64];
    const int tx = threadIdx.x;             // class 0..39
    const int ty = threadIdx.y;             // 0..7
    const int r0 = blockIdx.x * 64 + ty * 8;

    int rr[8];
    #pragma unroll
    for (int i = 0; i < 8; i++) {
        int r = r0 + i;
        rr[i] = (r < N_NODES) ? r : (N_NODES - 1);
    }

    float s[8] = {0.f, 0.f, 0.f, 0.f, 0.f, 0.f, 0.f, 0.f};
    for (int k = 0; k < H_LAT; k += 4) {
        float w0 = Wc[(k + 0) * N_CLASS + tx];
        float w1 = Wc[(k + 1) * N_CLASS + tx];
        float w2 = Wc[(k + 2) * N_CLASS + tx];
        float w3 = Wc[(k + 3) * N_CLASS + tx];
        #pragma unroll
        for (int i = 0; i < 8; i++) {
            const float4 a = *(const float4*)&g_accn[(size_t)rr[i] * H_LAT + k];
            s[i] += a.x * w0 + a.y * w1 + a.z * w2 + a.w * w3;
        }
    }
    const float b = bc[tx];
    #pragma unroll
    for (int i = 0; i < 8; i++) {
        zsh[ty * 8 + i][tx] = s[i] * 0.25f + b;   // /(NUM_LAYERS+1)
    }
    __syncthreads();

    int t = ty * 40 + tx;
    if (t < 64) {
        int gr = blockIdx.x * 64 + t;
        if (gr < N_NODES) {
            float m = zsh[t][0];
            #pragma unroll
            for (int cc = 1; cc < N_CLASS; cc++) m = fmaxf(m, zsh[t][cc]);
            float se = 0.f;
            #pragma unroll
            for (int cc = 0; cc < N_CLASS; cc++) se += expf(zsh[t][cc] - m);
            red[t] = m + logf(se);
        }
    }
    __syncthreads();

    #pragma unroll
    for (int i = 0; i < 8; i++) {
        int r = r0 + i;
        if (r < N_NODES)
            out[(size_t)r * N_CLASS + tx] = zsh[ty * 8 + i][tx] - red[ty * 8 + i];
    }
}

// ---------------- launch -----------------------------------------------------
extern "C" void kernel_launch(void* const* d_in, const int* in_sizes, int n_in,
                              void* d_out, int out_size) {
    const float* X     = (const float*)d_in[0];
    const float* W_red = (const float*)d_in[1];
    const float* b_red = (const float*)d_in[2];
    const float* W_cls = (const float*)d_in[3];
    const float* b_cls = (const float*)d_in[4];
    const float* evals = (const float*)d_in[5];
    const int*   erows = (const int*)  d_in[6];
    const int*   ecols = (const int*)  d_in[7];
    float* out = (float*)d_out;

    const int NBLK_SCAN = (N_TOTAL + 1023) / 1024;   // 147

    // CSR build
    k_zero_counts<<<(N_TOTAL + 255) / 256, 256>>>();
    k_hist<<<(NNZ + 255) / 256, 256>>>(erows);
    k_scan_a<<<NBLK_SCAN, 1024>>>();
    k_scan_b<<<1, 256>>>(NBLK_SCAN);
    k_scan_c<<<NBLK_SCAN, 1024>>>();
    k_fill<<<(NNZ + 255) / 256, 256>>>(erows, ecols, evals);

    // emb = X @ W_red + b_red (tf32 tensor cores)
    dim3 gG(H_LAT / 64, (N_TOTAL + 127) / 128);      // x = N tiles, y = M tiles
    k_gemm<<<gG, 256>>>(X, W_red, b_red);

    // 3 propagation layers (last layer: node rows only)
    dim3 sB(64, 4);
    k_spmm<<<dim3(N_TOTAL / 4, 2), sB>>>(0);
    k_spmm<<<dim3(N_TOTAL / 4, 2), sB>>>(1);
    k_spmm<<<dim3(N_NODES / 4, 2), sB>>>(2);

    // accn = emb + c1 + c2 + c3 (node rows)
    k_accsum<<<(N_NODES * (H_LAT/2) + 255) / 256, 256>>>();

    // classify + log_softmax
    dim3 cB(N_CLASS, 8);
    k_classify<<<(N_NODES + 63) / 64, cB>>>(W_cls, b_cls, out);
}